// round 8
// baseline (speedup 1.0000x reference)
#include <cuda_runtime.h>
#include <cuda_fp16.h>
#include <cuda_bf16.h>
#include <cstdint>
#include <cstdio>

#define DEV_INLINE __device__ __forceinline__

// ---------------------------------------------------------------------------
// Problem constants (fixed shapes)
// ---------------------------------------------------------------------------
constexpr int Bb   = 2;
constexpr int Ss   = 2048;
constexpr int HIDc = 2048;
constexpr int Hh   = 16;
constexpr int DNc  = 128;
constexpr int DRc  = 64;
constexpr int DVc  = 128;
constexpr int Rc   = 512;
constexpr int QHDc = DNc + DRc;   // 192
constexpr int MSc  = Bb * Ss;     // 4096 rows

// ---------------------------------------------------------------------------
// Scratch (static device globals; no allocation allowed)
// ---------------------------------------------------------------------------
__device__ __half g_hidden[MSc * HIDc];
__device__ __half g_Wq  [Hh * QHDc * HIDc];
__device__ __half g_Wkvd[Rc * HIDc];
__device__ __half g_Wkvu[Hh * QHDc * Rc];
__device__ __half g_Wkvv[Hh * DVc * Rc];
__device__ __half g_Wo  [HIDc * Hh * DVc];
__device__ __half g_q   [Bb * Hh * Ss * QHDc];
__device__ __half g_k   [Bb * Hh * Ss * QHDc];
__device__ __half g_v   [Bb * Hh * Ss * DVc];
__device__ float  g_ckv_raw[MSc * Rc];
__device__ __half g_ckv [MSc * Rc];
__device__ __half g_attn[MSc * Hh * DVc];

// ---------------------------------------------------------------------------
// PTX helpers
// ---------------------------------------------------------------------------
DEV_INLINE uint32_t saddr(const void* p) {
    return (uint32_t)__cvta_generic_to_shared(p);
}
DEV_INLINE void ldm_x4(uint32_t& r0, uint32_t& r1, uint32_t& r2, uint32_t& r3, uint32_t a) {
    asm volatile("ldmatrix.sync.aligned.m8n8.x4.shared.b16 {%0,%1,%2,%3}, [%4];\n"
                 : "=r"(r0), "=r"(r1), "=r"(r2), "=r"(r3) : "r"(a));
}
DEV_INLINE void ldm_x4t(uint32_t& r0, uint32_t& r1, uint32_t& r2, uint32_t& r3, uint32_t a) {
    asm volatile("ldmatrix.sync.aligned.m8n8.x4.trans.shared.b16 {%0,%1,%2,%3}, [%4];\n"
                 : "=r"(r0), "=r"(r1), "=r"(r2), "=r"(r3) : "r"(a));
}
DEV_INLINE void mma_f16(float c[4], const uint32_t a[4], const uint32_t b0, const uint32_t b1) {
    asm volatile(
        "mma.sync.aligned.m16n8k16.row.col.f32.f16.f16.f32 "
        "{%0,%1,%2,%3},{%4,%5,%6,%7},{%8,%9},{%0,%1,%2,%3};\n"
        : "+f"(c[0]), "+f"(c[1]), "+f"(c[2]), "+f"(c[3])
        : "r"(a[0]), "r"(a[1]), "r"(a[2]), "r"(a[3]), "r"(b0), "r"(b1));
}
DEV_INLINE uint32_t packh(float a, float b) {
    __half2 h = __floats2half2_rn(a, b);
    return *reinterpret_cast<uint32_t*>(&h);
}

// cp.async helpers
DEV_INLINE void cp16(uint32_t dst_smem, const void* src) {
    asm volatile("cp.async.cg.shared.global [%0], [%1], 16;\n"
                 :: "r"(dst_smem), "l"(src));
}
DEV_INLINE void cp_commit() {
    asm volatile("cp.async.commit_group;\n" ::: "memory");
}
template <int N>
DEV_INLINE void cp_wait() {
    asm volatile("cp.async.wait_group %0;\n" :: "n"(N) : "memory");
}

// ---------------------------------------------------------------------------
// Fused f32 -> f16 convert for all 6 tensors (one launch)
// ---------------------------------------------------------------------------
constexpr int N4_HID  = MSc * HIDc / 4;
constexpr int N4_WQ   = Hh * QHDc * HIDc / 4;
constexpr int N4_WKVD = Rc * HIDc / 4;
constexpr int N4_WKVU = Hh * QHDc * Rc / 4;
constexpr int N4_WKVV = Hh * DVc * Rc / 4;
constexpr int N4_WO   = HIDc * Hh * DVc / 4;
constexpr int N4_C0 = N4_HID;
constexpr int N4_C1 = N4_C0 + N4_WQ;
constexpr int N4_C2 = N4_C1 + N4_WKVD;
constexpr int N4_C3 = N4_C2 + N4_WKVU;
constexpr int N4_C4 = N4_C3 + N4_WKVV;
constexpr int N4_TOT = N4_C4 + N4_WO;

__global__ __launch_bounds__(256) void cvt_all_kernel(
    const float* __restrict__ hid, const float* __restrict__ wq,
    const float* __restrict__ wkvd, const float* __restrict__ wkvu,
    const float* __restrict__ wkvv, const float* __restrict__ wo,
    __half* __restrict__ d_hid, __half* __restrict__ d_wq,
    __half* __restrict__ d_wkvd, __half* __restrict__ d_wkvu,
    __half* __restrict__ d_wkvv, __half* __restrict__ d_wo) {
    int i = blockIdx.x * blockDim.x + threadIdx.x;
    if (i >= N4_TOT) return;
    const float* src;
    __half* dst;
    int j;
    if (i < N4_C0)      { src = hid;  dst = d_hid;  j = i; }
    else if (i < N4_C1) { src = wq;   dst = d_wq;   j = i - N4_C0; }
    else if (i < N4_C2) { src = wkvd; dst = d_wkvd; j = i - N4_C1; }
    else if (i < N4_C3) { src = wkvu; dst = d_wkvu; j = i - N4_C2; }
    else if (i < N4_C4) { src = wkvv; dst = d_wkvv; j = i - N4_C3; }
    else                { src = wo;   dst = d_wo;   j = i - N4_C4; }
    float4 v = reinterpret_cast<const float4*>(src)[j];
    __half2 a = __floats2half2_rn(v.x, v.y);
    __half2 b = __floats2half2_rn(v.z, v.w);
    reinterpret_cast<__half2*>(dst)[2 * j + 0] = a;
    reinterpret_cast<__half2*>(dst)[2 * j + 1] = b;
}

// ---------------------------------------------------------------------------
// RMSNorm over R=512, f32 in -> f16 out
// ---------------------------------------------------------------------------
__global__ __launch_bounds__(128) void rmsnorm_kernel(const float* __restrict__ raw,
                                                      const float* __restrict__ w,
                                                      __half* __restrict__ out) {
    int row = blockIdx.x;
    const float4* r4 = reinterpret_cast<const float4*>(raw + (size_t)row * Rc);
    float4 x = r4[threadIdx.x];
    float ss = x.x * x.x + x.y * x.y + x.z * x.z + x.w * x.w;
    #pragma unroll
    for (int o = 16; o; o >>= 1) ss += __shfl_xor_sync(0xffffffffu, ss, o);
    __shared__ float red[4];
    if ((threadIdx.x & 31) == 0) red[threadIdx.x >> 5] = ss;
    __syncthreads();
    float tot = red[0] + red[1] + red[2] + red[3];
    float inv = rsqrtf(tot * (1.0f / (float)Rc) + 1e-5f);
    float4 wv = reinterpret_cast<const float4*>(w)[threadIdx.x];
    __half2 h0 = __floats2half2_rn(x.x * inv * wv.x, x.y * inv * wv.y);
    __half2 h1 = __floats2half2_rn(x.z * inv * wv.z, x.w * inv * wv.w);
    __half2* op = reinterpret_cast<__half2*>(out + (size_t)row * Rc + threadIdx.x * 4);
    op[0] = h0;
    op[1] = h1;
}

// ---------------------------------------------------------------------------
// RoPE in-place on q AND k (both [B,H,S,QHD] f16), rope dims [128,192)
// ---------------------------------------------------------------------------
__global__ __launch_bounds__(256) void rope_kernel(__half* __restrict__ Xq,
                                                   __half* __restrict__ Xk,
                                                   const float* __restrict__ cosT,
                                                   const float* __restrict__ sinT) {
    int idx = blockIdx.x * blockDim.x + threadIdx.x;
    int j = idx & 31;
    int row = idx >> 5;
    const int nrows = Bb * Hh * Ss;
    if (row >= 2 * nrows) return;
    __half* X = (row < nrows) ? Xq : Xk;
    if (row >= nrows) row -= nrows;
    int s = row & (Ss - 1);
    __half* base = X + (size_t)row * QHDc + DNc;
    float x1 = __half2float(base[j]);
    float x2 = __half2float(base[j + 32]);
    float c1 = cosT[s * DRc + j];
    float s1 = sinT[s * DRc + j];
    float c2 = cosT[s * DRc + 32 + j];
    float s2 = sinT[s * DRc + 32 + j];
    base[j]      = __float2half_rn(x1 * c1 - x2 * s1);
    base[j + 32] = __float2half_rn(x2 * c2 + x1 * s2);
}

// ---------------------------------------------------------------------------
// NT GEMM, cp.async 3-stage pipeline, BK=64, coalesced smem-staged epilogue:
// C[M,N] = A[M,K] @ B[N,K]^T, f16 in, CTA tile 128x128, 8 warps (warp 32x64).
// EPI: 0 = f32 plain | 1 = f16 scatter [B,H,S,QHD] | 2 = f16 scatter [B,H,S,DV]
// ---------------------------------------------------------------------------
constexpr int GBK      = 64;
constexpr int SMST     = 72;                  // halves: 64 + 8 pad
constexpr int GSTAGES  = 3;
constexpr int STAGE_HALVES = 128 * SMST;      // 9216 per matrix per stage
constexpr int GEMM_SMEM = GSTAGES * 2 * STAGE_HALVES * (int)sizeof(__half);  // 110592
constexpr int EPI_F32_STRIDE = 132;           // floats per row (128 + 4 pad)
constexpr int EPI_F16_STRIDE = 136;           // halves per row (128 + 8 pad)
static_assert(128 * EPI_F32_STRIDE * 4 <= GEMM_SMEM, "f32 stage fits");

template <int EPI>
__global__ __launch_bounds__(256, 2) void gemm_nt(const __half* __restrict__ A,
                                                  const __half* __restrict__ Bw,
                                                  float* __restrict__ outF,
                                                  __half* __restrict__ outH,
                                                  int M, int N, int K) {
    extern __shared__ __half gsm[];

    const int tid = threadIdx.x;
    const int lane = tid & 31, warp = tid >> 5;
    const int wm = (warp & 3) * 32, wn = (warp >> 2) * 64;
    const int m0 = blockIdx.y * 128, n0 = blockIdx.x * 128;

    const __half* Ag = A + (size_t)m0 * K;
    const __half* Bg = Bw + (size_t)n0 * K;

    auto stageA = [&](int s) -> __half* { return gsm + s * 2 * STAGE_HALVES; };
    auto stageB = [&](int s) -> __half* { return gsm + s * 2 * STAGE_HALVES + STAGE_HALVES; };

    auto issue = [&](int s, int kc) {
        __half* sa = stageA(s);
        __half* sb = stageB(s);
        const __half* ag = Ag + (size_t)kc * GBK;
        const __half* bg = Bg + (size_t)kc * GBK;
        #pragma unroll
        for (int p = 0; p < 4; p++) {
            int idx = tid + p * 256;
            int r = idx >> 3;
            int c = (idx & 7) * 8;
            cp16(saddr(sa + r * SMST + c), ag + (size_t)r * K + c);
            cp16(saddr(sb + r * SMST + c), bg + (size_t)r * K + c);
        }
    };

    float acc[2][8][4];
    #pragma unroll
    for (int i = 0; i < 2; i++)
        #pragma unroll
        for (int j = 0; j < 8; j++)
            #pragma unroll
            for (int r = 0; r < 4; r++) acc[i][j][r] = 0.f;

    const int nk = K / GBK;

    issue(0, 0); cp_commit();
    issue(1, 1); cp_commit();

    for (int kc = 0; kc < nk; kc++) {
        cp_wait<1>();
        __syncthreads();
        const int s = kc % 3;
        const __half* sa = stageA(s);
        const __half* sb = stageB(s);

        #pragma unroll
        for (int ks = 0; ks < 4; ks++) {
            uint32_t af[2][4];
            #pragma unroll
            for (int mi = 0; mi < 2; mi++) {
                uint32_t a = saddr(&sa[(wm + mi * 16 + (lane & 15)) * SMST + ks * 16 + (lane >> 4) * 8]);
                ldm_x4(af[mi][0], af[mi][1], af[mi][2], af[mi][3], a);
            }
            uint32_t bf[8][2];
            #pragma unroll
            for (int j = 0; j < 4; j++) {
                uint32_t r0, r1, r2, r3;
                uint32_t a = saddr(&sb[(wn + j * 16 + (lane & 15)) * SMST + ks * 16 + (lane >> 4) * 8]);
                ldm_x4(r0, r1, r2, r3, a);
                bf[2 * j + 0][0] = r0; bf[2 * j + 0][1] = r2;
                bf[2 * j + 1][0] = r1; bf[2 * j + 1][1] = r3;
            }
            #pragma unroll
            for (int mi = 0; mi < 2; mi++)
                #pragma unroll
                for (int j = 0; j < 8; j++)
                    mma_f16(acc[mi][j], af[mi], bf[j][0], bf[j][1]);
        }

        if (kc + 2 < nk) issue((kc + 2) % 3, kc + 2);
        cp_commit();
    }

    // ---------------- epilogue: stage C in smem, write coalesced ------------
    cp_wait<0>();
    __syncthreads();

    const int g = lane >> 2, t = lane & 3;
    if (EPI == 0) {
        float* cs = reinterpret_cast<float*>(gsm);
        #pragma unroll
        for (int mi = 0; mi < 2; mi++)
            #pragma unroll
            for (int j = 0; j < 8; j++)
                #pragma unroll
                for (int hh = 0; hh < 2; hh++) {
                    int r = wm + mi * 16 + g + hh * 8;
                    int c = wn + j * 8 + t * 2;
                    cs[r * EPI_F32_STRIDE + c + 0] = acc[mi][j][hh * 2 + 0];
                    cs[r * EPI_F32_STRIDE + c + 1] = acc[mi][j][hh * 2 + 1];
                }
        __syncthreads();
        #pragma unroll
        for (int p = 0; p < 16; p++) {
            int chunk = tid + p * 256;
            int r = chunk >> 5, cc = (chunk & 31) * 4;
            float4 v = *reinterpret_cast<const float4*>(&cs[r * EPI_F32_STRIDE + cc]);
            *reinterpret_cast<float4*>(&outF[(size_t)(m0 + r) * N + n0 + cc]) = v;
        }
    } else {
        __half* cs = gsm;
        #pragma unroll
        for (int mi = 0; mi < 2; mi++)
            #pragma unroll
            for (int j = 0; j < 8; j++)
                #pragma unroll
                for (int hh = 0; hh < 2; hh++) {
                    int r = wm + mi * 16 + g + hh * 8;
                    int c = wn + j * 8 + t * 2;
                    *reinterpret_cast<__half2*>(&cs[r * EPI_F16_STRIDE + c]) =
                        __floats2half2_rn(acc[mi][j][hh * 2 + 0], acc[mi][j][hh * 2 + 1]);
                }
        __syncthreads();
        #pragma unroll
        for (int p = 0; p < 8; p++) {
            int chunk = tid + p * 256;
            int r = chunk >> 4, cc = (chunk & 15) * 8;
            uint4 v = *reinterpret_cast<const uint4*>(&cs[r * EPI_F16_STRIDE + cc]);
            int row = m0 + r;
            int col = n0 + cc;
            int b = row >> 11, s = row & (Ss - 1);
            size_t di;
            if (EPI == 1) {
                int h = col / QHDc, d = col - h * QHDc;
                di = (((size_t)b * Hh + h) * Ss + s) * QHDc + d;
            } else {
                int h = col >> 7, d = col & (DVc - 1);
                di = (((size_t)b * Hh + h) * Ss + s) * DVc + d;
            }
            *reinterpret_cast<uint4*>(&outH[di]) = v;
        }
    }
}

// ---------------------------------------------------------------------------
// Flash attention: per CTA one (b,h,qtile=128 rows). 8 warps, warp = 16 rows.
// K/V tiles of 64, synchronous loads, no-max exp2 softmax. 2 CTAs/SM.
// ---------------------------------------------------------------------------
constexpr int QSTRIDE = 200;  // 192 + 8 pad
constexpr int VSTRIDE = 136;  // 128 + 8 pad
constexpr int AQ_ROWS = 128;
constexpr int AK_ROWS = 64;
constexpr int ATTN_SMEM_BYTES =
    (AQ_ROWS * QSTRIDE + AK_ROWS * QSTRIDE + AK_ROWS * VSTRIDE) * (int)sizeof(__half); // 94208

__global__ __launch_bounds__(256, 2) void attn_kernel(const __half* __restrict__ Q,
                                                      const __half* __restrict__ Kt,
                                                      const __half* __restrict__ V,
                                                      __half* __restrict__ Out) {
    extern __shared__ __half sm[];
    __half* sQ = sm;
    __half* sK = sm + AQ_ROWS * QSTRIDE;
    __half* sV = sm + AQ_ROWS * QSTRIDE + AK_ROWS * QSTRIDE;

    const int qt = (int)gridDim.x - 1 - (int)blockIdx.x;  // heavy tiles first
    const int h = blockIdx.y, b = blockIdx.z;
    const int tid = threadIdx.x, lane = tid & 31, warp = tid >> 5;
    const int g = lane >> 2, t = lane & 3;
    const int wq = warp * 16;

    const size_t bh = (size_t)b * Hh + h;
    const __half* Qg = Q + (bh * Ss + (size_t)qt * AQ_ROWS) * QHDc;
    const __half* Kg = Kt + bh * Ss * QHDc;
    const __half* Vg = V + bh * Ss * DVc;

    // load Q tile: 128 rows x 24 chunks = 3072 chunks, 12 per thread
    #pragma unroll
    for (int p = 0; p < 12; p++) {
        int idx = tid + p * 256;
        int r = idx / 24, c = (idx % 24) * 8;
        *reinterpret_cast<uint4*>(&sQ[r * QSTRIDE + c]) =
            *reinterpret_cast<const uint4*>(&Qg[(size_t)r * QHDc + c]);
    }

    float o[16][4];
    #pragma unroll
    for (int i = 0; i < 16; i++)
        #pragma unroll
        for (int r = 0; r < 4; r++) o[i][r] = 0.f;
    float lrow[2] = {0.f, 0.f};
    const float scale2 = 0.07216878364870323f * 1.4426950408889634f;  // /sqrt(192)*log2e

    const int nkt = 2 * qt + 2;
    for (int kt = 0; kt < nkt; kt++) {
        __syncthreads();
        // K tile: 64 rows x 24 chunks = 1536 chunks, 6 per thread
        #pragma unroll
        for (int p = 0; p < 6; p++) {
            int idx = tid + p * 256;
            int r = idx / 24, c = (idx % 24) * 8;
            *reinterpret_cast<uint4*>(&sK[r * QSTRIDE + c]) =
                *reinterpret_cast<const uint4*>(&Kg[((size_t)kt * AK_ROWS + r) * QHDc + c]);
        }
        // V tile: 64 rows x 16 chunks = 1024 chunks, 4 per thread
        #pragma unroll
        for (int p = 0; p < 4; p++) {
            int idx = tid + p * 256;
            int r = idx >> 4, c = (idx & 15) * 8;
            *reinterpret_cast<uint4*>(&sV[r * VSTRIDE + c]) =
                *reinterpret_cast<const uint4*>(&Vg[((size_t)kt * AK_ROWS + r) * DVc + c]);
        }
        __syncthreads();

        float sacc[8][4];
        #pragma unroll
        for (int j = 0; j < 8; j++)
            #pragma unroll
            for (int r = 0; r < 4; r++) sacc[j][r] = 0.f;

        #pragma unroll
        for (int ks = 0; ks < 12; ks++) {
            uint32_t af[4];
            ldm_x4(af[0], af[1], af[2], af[3],
                   saddr(&sQ[(wq + (lane & 15)) * QSTRIDE + ks * 16 + (lane >> 4) * 8]));
            #pragma unroll
            for (int j = 0; j < 4; j++) {
                uint32_t r0, r1, r2, r3;
                ldm_x4(r0, r1, r2, r3,
                       saddr(&sK[(j * 16 + (lane & 15)) * QSTRIDE + ks * 16 + (lane >> 4) * 8]));
                mma_f16(sacc[2 * j + 0], af, r0, r2);
                mma_f16(sacc[2 * j + 1], af, r1, r3);
            }
        }

        // p = exp2(score * scale2); masked entries -> 0
        const bool diag = (kt >= 2 * qt);
        #pragma unroll
        for (int hh = 0; hh < 2; hh++) {
            float sum = 0.f;
            #pragma unroll
            for (int j = 0; j < 8; j++) {
                float s0 = sacc[j][hh * 2 + 0] * scale2;
                float s1 = sacc[j][hh * 2 + 1] * scale2;
                if (diag) {
                    int col = kt * AK_ROWS + j * 8 + t * 2;
                    int qrow = qt * AQ_ROWS + wq + g + hh * 8;
                    if (col > qrow)     s0 = -1e30f;
                    if (col + 1 > qrow) s1 = -1e30f;
                }
                float p0 = exp2f(s0);
                float p1 = exp2f(s1);
                sacc[j][hh * 2 + 0] = p0;
                sacc[j][hh * 2 + 1] = p1;
                sum += p0 + p1;
            }
            sum += __shfl_xor_sync(0xffffffffu, sum, 1);
            sum += __shfl_xor_sync(0xffffffffu, sum, 2);
            lrow[hh] += sum;
        }

        uint32_t pa[4][4];
        #pragma unroll
        for (int kk = 0; kk < 4; kk++) {
            pa[kk][0] = packh(sacc[2 * kk][0], sacc[2 * kk][1]);
            pa[kk][1] = packh(sacc[2 * kk][2], sacc[2 * kk][3]);
            pa[kk][2] = packh(sacc[2 * kk + 1][0], sacc[2 * kk + 1][1]);
            pa[kk][3] = packh(sacc[2 * kk + 1][2], sacc[2 * kk + 1][3]);
        }

        #pragma unroll
        for (int kk = 0; kk < 4; kk++) {
            #pragma unroll
            for (int jg = 0; jg < 8; jg++) {
                uint32_t r0, r1, r2, r3;
                ldm_x4t(r0, r1, r2, r3,
                        saddr(&sV[(kk * 16 + (lane & 15)) * VSTRIDE + jg * 16 + (lane >> 4) * 8]));
                mma_f16(o[2 * jg + 0], pa[kk], r0, r1);
                mma_f16(o[2 * jg + 1], pa[kk], r2, r3);
            }
        }
    }

    float inv0 = 1.f / lrow[0];
    float inv1 = 1.f / lrow[1];
    #pragma unroll
    for (int nt = 0; nt < 16; nt++) {
        #pragma unroll
        for (int hh = 0; hh < 2; hh++) {
            float inv = hh ? inv1 : inv0;
            int srow = qt * AQ_ROWS + wq + g + hh * 8;
            int col = nt * 8 + t * 2;
            __half2 hv = __floats2half2_rn(o[nt][hh * 2] * inv, o[nt][hh * 2 + 1] * inv);
            size_t di = ((size_t)b * Ss + srow) * (Hh * DVc) + (size_t)h * DVc + col;
            *reinterpret_cast<__half2*>(&Out[di]) = hv;
        }
    }
}

// ---------------------------------------------------------------------------
// Host launcher
// ---------------------------------------------------------------------------
static void* symaddr(const void* sym) {
    void* p = nullptr;
    cudaGetSymbolAddress(&p, sym);
    return p;
}

extern "C" void kernel_launch(void* const* d_in, const int* in_sizes, int n_in,
                              void* d_out, int out_size) {
    const float* hidden = (const float*)d_in[0];
    const float* Wq    = (const float*)d_in[3];
    const float* Wkvd  = (const float*)d_in[4];
    const float* normw = (const float*)d_in[5];
    const float* Wkvu  = (const float*)d_in[6];
    const float* Wkvv  = (const float*)d_in[7];
    const float* Wo    = (const float*)d_in[8];
    const float* cosT  = (const float*)d_in[9];
    const float* sinT  = (const float*)d_in[10];
    float* out = (float*)d_out;

    __half* p_hidden = (__half*)symaddr(g_hidden);
    __half* p_Wq     = (__half*)symaddr(g_Wq);
    __half* p_Wkvd   = (__half*)symaddr(g_Wkvd);
    __half* p_Wkvu   = (__half*)symaddr(g_Wkvu);
    __half* p_Wkvv   = (__half*)symaddr(g_Wkvv);
    __half* p_Wo     = (__half*)symaddr(g_Wo);
    __half* p_q      = (__half*)symaddr(g_q);
    __half* p_k      = (__half*)symaddr(g_k);
    __half* p_v      = (__half*)symaddr(g_v);
    float*  p_ckvraw = (float*) symaddr(g_ckv_raw);
    __half* p_ckv    = (__half*)symaddr(g_ckv);
    __half* p_attn   = (__half*)symaddr(g_attn);

    // launch 0: fused convert
    cvt_all_kernel<<<(N4_TOT + 255) / 256, 256>>>(
        hidden, Wq, Wkvd, Wkvu, Wkvv, Wo,
        p_hidden, p_Wq, p_Wkvd, p_Wkvu, p_Wkvv, p_Wo);

    cudaFuncSetAttribute(gemm_nt<0>, cudaFuncAttributeMaxDynamicSharedMemorySize, GEMM_SMEM);
    cudaFuncSetAttribute(gemm_nt<1>, cudaFuncAttributeMaxDynamicSharedMemorySize, GEMM_SMEM);
    cudaFuncSetAttribute(gemm_nt<2>, cudaFuncAttributeMaxDynamicSharedMemorySize, GEMM_SMEM);

    // launch 1: ckv_raw = hidden @ Wkv_down^T (f32)
    gemm_nt<0><<<dim3(Rc / 128, MSc / 128), 256, GEMM_SMEM>>>(
        p_hidden, p_Wkvd, p_ckvraw, nullptr, MSc, Rc, HIDc);
    // launch 2: rmsnorm
    rmsnorm_kernel<<<MSc, 128>>>(p_ckvraw, normw, p_ckv);
    // launch 3: k = ckv @ Wkv_up^T -> scatter [B,H,S,QHD]   (PROFILED, idx 3)
    gemm_nt<1><<<dim3((Hh * QHDc) / 128, MSc / 128), 256, GEMM_SMEM>>>(
        p_ckv, p_Wkvu, nullptr, p_k, MSc, Hh * QHDc, Rc);
    // launch 4: q = hidden @ Wq^T -> scatter [B,H,S,QHD]
    gemm_nt<1><<<dim3((Hh * QHDc) / 128, MSc / 128), 256, GEMM_SMEM>>>(
        p_hidden, p_Wq, nullptr, p_q, MSc, Hh * QHDc, HIDc);
    // launch 5: v = ckv @ Wkv_v^T -> scatter [B,H,S,DV]
    gemm_nt<2><<<dim3((Hh * DVc) / 128, MSc / 128), 256, GEMM_SMEM>>>(
        p_ckv, p_Wkvv, nullptr, p_v, MSc, Hh * DVc, Rc);
    // launch 6: RoPE on q and k (fused)
    {
        int total = 2 * Bb * Hh * Ss * 32;
        rope_kernel<<<(total + 255) / 256, 256>>>(p_q, p_k, cosT, sinT);
    }
    // launch 7: attention (128-row Q tiles, 8 warps, 2 CTAs/SM)
    cudaFuncSetAttribute(attn_kernel, cudaFuncAttributeMaxDynamicSharedMemorySize,
                         ATTN_SMEM_BYTES);
    attn_kernel<<<dim3(Ss / AQ_ROWS, Hh, Bb), 256, ATTN_SMEM_BYTES>>>(p_q, p_k, p_v, p_attn);
    // launch 8: out = attn @ Wo^T (f32, straight to d_out)
    gemm_nt<0><<<dim3(HIDc / 128, MSc / 128), 256, GEMM_SMEM>>>(
        p_attn, p_Wo, out, nullptr, MSc, HIDc, HIDc);
}

// round 9
// speedup vs baseline: 1.0515x; 1.0515x over previous
#include <cuda_runtime.h>
#include <cuda_fp16.h>
#include <cuda_bf16.h>
#include <cstdint>
#include <cstdio>

#define DEV_INLINE __device__ __forceinline__

// ---------------------------------------------------------------------------
// Problem constants (fixed shapes)
// ---------------------------------------------------------------------------
constexpr int Bb   = 2;
constexpr int Ss   = 2048;
constexpr int HIDc = 2048;
constexpr int Hh   = 16;
constexpr int DNc  = 128;
constexpr int DRc  = 64;
constexpr int DVc  = 128;
constexpr int Rc   = 512;
constexpr int QHDc = DNc + DRc;   // 192
constexpr int MSc  = Bb * Ss;     // 4096 rows
constexpr int NKV  = Hh * QHDc + Hh * DVc;  // 5120 merged k|v output cols

// ---------------------------------------------------------------------------
// Scratch (static device globals; no allocation allowed)
// ---------------------------------------------------------------------------
__device__ __half g_hidden[MSc * HIDc];
__device__ __half g_Wq  [Hh * QHDc * HIDc];
__device__ __half g_Wkvd[Rc * HIDc];
__device__ __half g_Wkvuv[NKV * Rc];          // rows 0..3071 = Wkv_up, 3072..5119 = Wkv_v
__device__ __half g_Wo  [HIDc * Hh * DVc];
__device__ __half g_q   [Bb * Hh * Ss * QHDc];
__device__ __half g_k   [Bb * Hh * Ss * QHDc];
__device__ __half g_v   [Bb * Hh * Ss * DVc];
__device__ float  g_ckv_raw[MSc * Rc];
__device__ __half g_ckv [MSc * Rc];
__device__ __half g_attn[MSc * Hh * DVc];

// ---------------------------------------------------------------------------
// PTX helpers
// ---------------------------------------------------------------------------
DEV_INLINE uint32_t saddr(const void* p) {
    return (uint32_t)__cvta_generic_to_shared(p);
}
DEV_INLINE void ldm_x4(uint32_t& r0, uint32_t& r1, uint32_t& r2, uint32_t& r3, uint32_t a) {
    asm volatile("ldmatrix.sync.aligned.m8n8.x4.shared.b16 {%0,%1,%2,%3}, [%4];\n"
                 : "=r"(r0), "=r"(r1), "=r"(r2), "=r"(r3) : "r"(a));
}
DEV_INLINE void ldm_x4t(uint32_t& r0, uint32_t& r1, uint32_t& r2, uint32_t& r3, uint32_t a) {
    asm volatile("ldmatrix.sync.aligned.m8n8.x4.trans.shared.b16 {%0,%1,%2,%3}, [%4];\n"
                 : "=r"(r0), "=r"(r1), "=r"(r2), "=r"(r3) : "r"(a));
}
DEV_INLINE void mma_f16(float c[4], const uint32_t a[4], const uint32_t b0, const uint32_t b1) {
    asm volatile(
        "mma.sync.aligned.m16n8k16.row.col.f32.f16.f16.f32 "
        "{%0,%1,%2,%3},{%4,%5,%6,%7},{%8,%9},{%0,%1,%2,%3};\n"
        : "+f"(c[0]), "+f"(c[1]), "+f"(c[2]), "+f"(c[3])
        : "r"(a[0]), "r"(a[1]), "r"(a[2]), "r"(a[3]), "r"(b0), "r"(b1));
}
DEV_INLINE uint32_t packh(float a, float b) {
    __half2 h = __floats2half2_rn(a, b);
    return *reinterpret_cast<uint32_t*>(&h);
}

// cp.async helpers
DEV_INLINE void cp16(uint32_t dst_smem, const void* src) {
    asm volatile("cp.async.cg.shared.global [%0], [%1], 16;\n"
                 :: "r"(dst_smem), "l"(src));
}
DEV_INLINE void cp_commit() {
    asm volatile("cp.async.commit_group;\n" ::: "memory");
}
template <int N>
DEV_INLINE void cp_wait() {
    asm volatile("cp.async.wait_group %0;\n" :: "n"(N) : "memory");
}

// ---------------------------------------------------------------------------
// Fused f32 -> f16 convert for all 6 tensors (one launch)
// Wkv_up and Wkv_v are written into the single merged buffer g_Wkvuv.
// ---------------------------------------------------------------------------
constexpr int N4_HID  = MSc * HIDc / 4;
constexpr int N4_WQ   = Hh * QHDc * HIDc / 4;
constexpr int N4_WKVD = Rc * HIDc / 4;
constexpr int N4_WKVU = Hh * QHDc * Rc / 4;
constexpr int N4_WKVV = Hh * DVc * Rc / 4;
constexpr int N4_WO   = HIDc * Hh * DVc / 4;
constexpr int N4_C0 = N4_HID;
constexpr int N4_C1 = N4_C0 + N4_WQ;
constexpr int N4_C2 = N4_C1 + N4_WKVD;
constexpr int N4_C3 = N4_C2 + N4_WKVU;
constexpr int N4_C4 = N4_C3 + N4_WKVV;
constexpr int N4_TOT = N4_C4 + N4_WO;

__global__ __launch_bounds__(256) void cvt_all_kernel(
    const float* __restrict__ hid, const float* __restrict__ wq,
    const float* __restrict__ wkvd, const float* __restrict__ wkvu,
    const float* __restrict__ wkvv, const float* __restrict__ wo,
    __half* __restrict__ d_hid, __half* __restrict__ d_wq,
    __half* __restrict__ d_wkvd, __half* __restrict__ d_wkvuv,
    __half* __restrict__ d_wo) {
    int i = blockIdx.x * blockDim.x + threadIdx.x;
    if (i >= N4_TOT) return;
    const float* src;
    __half* dst;
    int j;
    if (i < N4_C0)      { src = hid;  dst = d_hid;  j = i; }
    else if (i < N4_C1) { src = wq;   dst = d_wq;   j = i - N4_C0; }
    else if (i < N4_C2) { src = wkvd; dst = d_wkvd; j = i - N4_C1; }
    else if (i < N4_C3) { src = wkvu; dst = d_wkvuv; j = i - N4_C2; }
    else if (i < N4_C4) { src = wkvv; dst = d_wkvuv + Hh * QHDc * Rc; j = i - N4_C3; }
    else                { src = wo;   dst = d_wo;   j = i - N4_C4; }
    float4 v = reinterpret_cast<const float4*>(src)[j];
    __half2 a = __floats2half2_rn(v.x, v.y);
    __half2 b = __floats2half2_rn(v.z, v.w);
    reinterpret_cast<__half2*>(dst)[2 * j + 0] = a;
    reinterpret_cast<__half2*>(dst)[2 * j + 1] = b;
}

// ---------------------------------------------------------------------------
// RMSNorm over R=512, f32 in -> f16 out
// ---------------------------------------------------------------------------
__global__ __launch_bounds__(128) void rmsnorm_kernel(const float* __restrict__ raw,
                                                      const float* __restrict__ w,
                                                      __half* __restrict__ out) {
    int row = blockIdx.x;
    const float4* r4 = reinterpret_cast<const float4*>(raw + (size_t)row * Rc);
    float4 x = r4[threadIdx.x];
    float ss = x.x * x.x + x.y * x.y + x.z * x.z + x.w * x.w;
    #pragma unroll
    for (int o = 16; o; o >>= 1) ss += __shfl_xor_sync(0xffffffffu, ss, o);
    __shared__ float red[4];
    if ((threadIdx.x & 31) == 0) red[threadIdx.x >> 5] = ss;
    __syncthreads();
    float tot = red[0] + red[1] + red[2] + red[3];
    float inv = rsqrtf(tot * (1.0f / (float)Rc) + 1e-5f);
    float4 wv = reinterpret_cast<const float4*>(w)[threadIdx.x];
    __half2 h0 = __floats2half2_rn(x.x * inv * wv.x, x.y * inv * wv.y);
    __half2 h1 = __floats2half2_rn(x.z * inv * wv.z, x.w * inv * wv.w);
    __half2* op = reinterpret_cast<__half2*>(out + (size_t)row * Rc + threadIdx.x * 4);
    op[0] = h0;
    op[1] = h1;
}

// ---------------------------------------------------------------------------
// RoPE in-place on q AND k (both [B,H,S,QHD] f16), rope dims [128,192)
// ---------------------------------------------------------------------------
__global__ __launch_bounds__(256) void rope_kernel(__half* __restrict__ Xq,
                                                   __half* __restrict__ Xk,
                                                   const float* __restrict__ cosT,
                                                   const float* __restrict__ sinT) {
    int idx = blockIdx.x * blockDim.x + threadIdx.x;
    int j = idx & 31;
    int row = idx >> 5;
    const int nrows = Bb * Hh * Ss;
    if (row >= 2 * nrows) return;
    __half* X = (row < nrows) ? Xq : Xk;
    if (row >= nrows) row -= nrows;
    int s = row & (Ss - 1);
    __half* base = X + (size_t)row * QHDc + DNc;
    float x1 = __half2float(base[j]);
    float x2 = __half2float(base[j + 32]);
    float c1 = cosT[s * DRc + j];
    float s1 = sinT[s * DRc + j];
    float c2 = cosT[s * DRc + 32 + j];
    float s2 = sinT[s * DRc + 32 + j];
    base[j]      = __float2half_rn(x1 * c1 - x2 * s1);
    base[j + 32] = __float2half_rn(x2 * c2 + x1 * s2);
}

// ---------------------------------------------------------------------------
// NT GEMM, cp.async 3-stage pipeline, BK=64, coalesced smem-staged epilogue:
// C[M,N] = A[M,K] @ B[N,K]^T, f16 in, CTA tile 128x128, 8 warps (warp 32x64).
// EPI: 0 = f32 plain | 1 = f16 scatter [B,H,S,QHD]
//      3 = merged k|v scatter: col<3072 -> g_k [B,H,S,QHD], else -> g_v [B,H,S,DV]
// ---------------------------------------------------------------------------
constexpr int GBK      = 64;
constexpr int SMST     = 72;                  // halves: 64 + 8 pad
constexpr int GSTAGES  = 3;
constexpr int STAGE_HALVES = 128 * SMST;      // 9216 per matrix per stage
constexpr int GEMM_SMEM = GSTAGES * 2 * STAGE_HALVES * (int)sizeof(__half);  // 110592
constexpr int EPI_F32_STRIDE = 132;           // floats per row (128 + 4 pad)
constexpr int EPI_F16_STRIDE = 136;           // halves per row (128 + 8 pad)
static_assert(128 * EPI_F32_STRIDE * 4 <= GEMM_SMEM, "f32 stage fits");

template <int EPI>
__global__ __launch_bounds__(256, 2) void gemm_nt(const __half* __restrict__ A,
                                                  const __half* __restrict__ Bw,
                                                  float* __restrict__ outF,
                                                  __half* __restrict__ outH,
                                                  int M, int N, int K) {
    extern __shared__ __half gsm[];

    const int tid = threadIdx.x;
    const int lane = tid & 31, warp = tid >> 5;
    const int wm = (warp & 3) * 32, wn = (warp >> 2) * 64;
    const int m0 = blockIdx.y * 128, n0 = blockIdx.x * 128;

    const __half* Ag = A + (size_t)m0 * K;
    const __half* Bg = Bw + (size_t)n0 * K;

    auto stageA = [&](int s) -> __half* { return gsm + s * 2 * STAGE_HALVES; };
    auto stageB = [&](int s) -> __half* { return gsm + s * 2 * STAGE_HALVES + STAGE_HALVES; };

    auto issue = [&](int s, int kc) {
        __half* sa = stageA(s);
        __half* sb = stageB(s);
        const __half* ag = Ag + (size_t)kc * GBK;
        const __half* bg = Bg + (size_t)kc * GBK;
        #pragma unroll
        for (int p = 0; p < 4; p++) {
            int idx = tid + p * 256;
            int r = idx >> 3;
            int c = (idx & 7) * 8;
            cp16(saddr(sa + r * SMST + c), ag + (size_t)r * K + c);
            cp16(saddr(sb + r * SMST + c), bg + (size_t)r * K + c);
        }
    };

    float acc[2][8][4];
    #pragma unroll
    for (int i = 0; i < 2; i++)
        #pragma unroll
        for (int j = 0; j < 8; j++)
            #pragma unroll
            for (int r = 0; r < 4; r++) acc[i][j][r] = 0.f;

    const int nk = K / GBK;

    issue(0, 0); cp_commit();
    issue(1, 1); cp_commit();

    for (int kc = 0; kc < nk; kc++) {
        cp_wait<1>();
        __syncthreads();
        const int s = kc % 3;
        const __half* sa = stageA(s);
        const __half* sb = stageB(s);

        #pragma unroll
        for (int ks = 0; ks < 4; ks++) {
            uint32_t af[2][4];
            #pragma unroll
            for (int mi = 0; mi < 2; mi++) {
                uint32_t a = saddr(&sa[(wm + mi * 16 + (lane & 15)) * SMST + ks * 16 + (lane >> 4) * 8]);
                ldm_x4(af[mi][0], af[mi][1], af[mi][2], af[mi][3], a);
            }
            uint32_t bf[8][2];
            #pragma unroll
            for (int j = 0; j < 4; j++) {
                uint32_t r0, r1, r2, r3;
                uint32_t a = saddr(&sb[(wn + j * 16 + (lane & 15)) * SMST + ks * 16 + (lane >> 4) * 8]);
                ldm_x4(r0, r1, r2, r3, a);
                bf[2 * j + 0][0] = r0; bf[2 * j + 0][1] = r2;
                bf[2 * j + 1][0] = r1; bf[2 * j + 1][1] = r3;
            }
            #pragma unroll
            for (int mi = 0; mi < 2; mi++)
                #pragma unroll
                for (int j = 0; j < 8; j++)
                    mma_f16(acc[mi][j], af[mi], bf[j][0], bf[j][1]);
        }

        if (kc + 2 < nk) issue((kc + 2) % 3, kc + 2);
        cp_commit();
    }

    // ---------------- epilogue: stage C in smem, write coalesced ------------
    cp_wait<0>();
    __syncthreads();

    const int g = lane >> 2, t = lane & 3;
    if (EPI == 0) {
        float* cs = reinterpret_cast<float*>(gsm);
        #pragma unroll
        for (int mi = 0; mi < 2; mi++)
            #pragma unroll
            for (int j = 0; j < 8; j++)
                #pragma unroll
                for (int hh = 0; hh < 2; hh++) {
                    int r = wm + mi * 16 + g + hh * 8;
                    int c = wn + j * 8 + t * 2;
                    cs[r * EPI_F32_STRIDE + c + 0] = acc[mi][j][hh * 2 + 0];
                    cs[r * EPI_F32_STRIDE + c + 1] = acc[mi][j][hh * 2 + 1];
                }
        __syncthreads();
        #pragma unroll
        for (int p = 0; p < 16; p++) {
            int chunk = tid + p * 256;
            int r = chunk >> 5, cc = (chunk & 31) * 4;
            float4 v = *reinterpret_cast<const float4*>(&cs[r * EPI_F32_STRIDE + cc]);
            *reinterpret_cast<float4*>(&outF[(size_t)(m0 + r) * N + n0 + cc]) = v;
        }
    } else {
        __half* cs = gsm;
        #pragma unroll
        for (int mi = 0; mi < 2; mi++)
            #pragma unroll
            for (int j = 0; j < 8; j++)
                #pragma unroll
                for (int hh = 0; hh < 2; hh++) {
                    int r = wm + mi * 16 + g + hh * 8;
                    int c = wn + j * 8 + t * 2;
                    *reinterpret_cast<__half2*>(&cs[r * EPI_F16_STRIDE + c]) =
                        __floats2half2_rn(acc[mi][j][hh * 2 + 0], acc[mi][j][hh * 2 + 1]);
                }
        __syncthreads();
        #pragma unroll
        for (int p = 0; p < 8; p++) {
            int chunk = tid + p * 256;
            int r = chunk >> 4, cc = (chunk & 15) * 8;
            uint4 v = *reinterpret_cast<const uint4*>(&cs[r * EPI_F16_STRIDE + cc]);
            int row = m0 + r;
            int col = n0 + cc;
            int b = row >> 11, s = row & (Ss - 1);
            if (EPI == 1) {
                int h = col / QHDc, d = col - h * QHDc;
                size_t di = (((size_t)b * Hh + h) * Ss + s) * QHDc + d;
                *reinterpret_cast<uint4*>(&outH[di]) = v;
            } else {  // EPI == 3: merged k|v scatter via device globals
                if (col < Hh * QHDc) {
                    int h = col / QHDc, d = col - h * QHDc;
                    size_t di = (((size_t)b * Hh + h) * Ss + s) * QHDc + d;
                    *reinterpret_cast<uint4*>(&g_k[di]) = v;
                } else {
                    int c2 = col - Hh * QHDc;
                    int h = c2 >> 7, d = c2 & (DVc - 1);
                    size_t di = (((size_t)b * Hh + h) * Ss + s) * DVc + d;
                    *reinterpret_cast<uint4*>(&g_v[di]) = v;
                }
            }
        }
    }
}

// ---------------------------------------------------------------------------
// Flash attention (R7 config — measured best): per CTA one (b,h,qtile=64 rows).
// 4 warps, 3 CTAs/SM, no-max exp2 softmax.
// ---------------------------------------------------------------------------
constexpr int QSTRIDE = 200;  // 192 + 8 pad
constexpr int VSTRIDE = 136;  // 128 + 8 pad
constexpr int ATTN_SMEM_BYTES = (64 * QSTRIDE * 2 + 64 * VSTRIDE) * (int)sizeof(__half);

__global__ __launch_bounds__(128, 3) void attn_kernel(const __half* __restrict__ Q,
                                                      const __half* __restrict__ Kt,
                                                      const __half* __restrict__ V,
                                                      __half* __restrict__ Out) {
    extern __shared__ __half sm[];
    __half* sQ = sm;
    __half* sK = sm + 64 * QSTRIDE;
    __half* sV = sm + 2 * 64 * QSTRIDE;

    const int qt = (int)gridDim.x - 1 - (int)blockIdx.x;  // heavy tiles first
    const int h = blockIdx.y, b = blockIdx.z;
    const int tid = threadIdx.x, lane = tid & 31, warp = tid >> 5;
    const int g = lane >> 2, t = lane & 3;
    const int wq = warp * 16;

    const size_t bh = (size_t)b * Hh + h;
    const __half* Qg = Q + (bh * Ss + (size_t)qt * 64) * QHDc;
    const __half* Kg = Kt + bh * Ss * QHDc;
    const __half* Vg = V + bh * Ss * DVc;

    #pragma unroll
    for (int p = 0; p < 12; p++) {
        int idx = tid + p * 128;
        int r = idx / 24, c = (idx % 24) * 8;
        *reinterpret_cast<uint4*>(&sQ[r * QSTRIDE + c]) =
            *reinterpret_cast<const uint4*>(&Qg[(size_t)r * QHDc + c]);
    }

    float o[16][4];
    #pragma unroll
    for (int i = 0; i < 16; i++)
        #pragma unroll
        for (int r = 0; r < 4; r++) o[i][r] = 0.f;
    float lrow[2] = {0.f, 0.f};
    const float scale2 = 0.07216878364870323f * 1.4426950408889634f;  // /sqrt(192)*log2e

    const int nkt = qt + 1;
    for (int kt = 0; kt < nkt; kt++) {
        __syncthreads();
        #pragma unroll
        for (int p = 0; p < 12; p++) {
            int idx = tid + p * 128;
            int r = idx / 24, c = (idx % 24) * 8;
            *reinterpret_cast<uint4*>(&sK[r * QSTRIDE + c]) =
                *reinterpret_cast<const uint4*>(&Kg[((size_t)kt * 64 + r) * QHDc + c]);
        }
        #pragma unroll
        for (int p = 0; p < 8; p++) {
            int idx = tid + p * 128;
            int r = idx >> 4, c = (idx & 15) * 8;
            *reinterpret_cast<uint4*>(&sV[r * VSTRIDE + c]) =
                *reinterpret_cast<const uint4*>(&Vg[((size_t)kt * 64 + r) * DVc + c]);
        }
        __syncthreads();

        float sacc[8][4];
        #pragma unroll
        for (int j = 0; j < 8; j++)
            #pragma unroll
            for (int r = 0; r < 4; r++) sacc[j][r] = 0.f;

        #pragma unroll
        for (int ks = 0; ks < 12; ks++) {
            uint32_t af[4];
            ldm_x4(af[0], af[1], af[2], af[3],
                   saddr(&sQ[(wq + (lane & 15)) * QSTRIDE + ks * 16 + (lane >> 4) * 8]));
            #pragma unroll
            for (int j = 0; j < 4; j++) {
                uint32_t r0, r1, r2, r3;
                ldm_x4(r0, r1, r2, r3,
                       saddr(&sK[(j * 16 + (lane & 15)) * QSTRIDE + ks * 16 + (lane >> 4) * 8]));
                mma_f16(sacc[2 * j + 0], af, r0, r2);
                mma_f16(sacc[2 * j + 1], af, r1, r3);
            }
        }

        const bool diag = (kt == qt);
        #pragma unroll
        for (int hh = 0; hh < 2; hh++) {
            float sum = 0.f;
            #pragma unroll
            for (int j = 0; j < 8; j++) {
                float s0 = sacc[j][hh * 2 + 0] * scale2;
                float s1 = sacc[j][hh * 2 + 1] * scale2;
                if (diag) {
                    int col = kt * 64 + j * 8 + t * 2;
                    int qrow = qt * 64 + wq + g + hh * 8;
                    if (col > qrow)     s0 = -1e30f;
                    if (col + 1 > qrow) s1 = -1e30f;
                }
                float p0 = exp2f(s0);
                float p1 = exp2f(s1);
                sacc[j][hh * 2 + 0] = p0;
                sacc[j][hh * 2 + 1] = p1;
                sum += p0 + p1;
            }
            sum += __shfl_xor_sync(0xffffffffu, sum, 1);
            sum += __shfl_xor_sync(0xffffffffu, sum, 2);
            lrow[hh] += sum;
        }

        uint32_t pa[4][4];
        #pragma unroll
        for (int kk = 0; kk < 4; kk++) {
            pa[kk][0] = packh(sacc[2 * kk][0], sacc[2 * kk][1]);
            pa[kk][1] = packh(sacc[2 * kk][2], sacc[2 * kk][3]);
            pa[kk][2] = packh(sacc[2 * kk + 1][0], sacc[2 * kk + 1][1]);
            pa[kk][3] = packh(sacc[2 * kk + 1][2], sacc[2 * kk + 1][3]);
        }

        #pragma unroll
        for (int kk = 0; kk < 4; kk++) {
            #pragma unroll
            for (int jg = 0; jg < 8; jg++) {
                uint32_t r0, r1, r2, r3;
                ldm_x4t(r0, r1, r2, r3,
                        saddr(&sV[(kk * 16 + (lane & 15)) * VSTRIDE + jg * 16 + (lane >> 4) * 8]));
                mma_f16(o[2 * jg + 0], pa[kk], r0, r1);
                mma_f16(o[2 * jg + 1], pa[kk], r2, r3);
            }
        }
    }

    float inv0 = 1.f / lrow[0];
    float inv1 = 1.f / lrow[1];
    #pragma unroll
    for (int nt = 0; nt < 16; nt++) {
        #pragma unroll
        for (int hh = 0; hh < 2; hh++) {
            float inv = hh ? inv1 : inv0;
            int srow = qt * 64 + wq + g + hh * 8;
            int col = nt * 8 + t * 2;
            __half2 hv = __floats2half2_rn(o[nt][hh * 2] * inv, o[nt][hh * 2 + 1] * inv);
            size_t di = ((size_t)b * Ss + srow) * (Hh * DVc) + (size_t)h * DVc + col;
            *reinterpret_cast<__half2*>(&Out[di]) = hv;
        }
    }
}

// ---------------------------------------------------------------------------
// Host launcher
// ---------------------------------------------------------------------------
static void* symaddr(const void* sym) {
    void* p = nullptr;
    cudaGetSymbolAddress(&p, sym);
    return p;
}

extern "C" void kernel_launch(void* const* d_in, const int* in_sizes, int n_in,
                              void* d_out, int out_size) {
    const float* hidden = (const float*)d_in[0];
    const float* Wq    = (const float*)d_in[3];
    const float* Wkvd  = (const float*)d_in[4];
    const float* normw = (const float*)d_in[5];
    const float* Wkvu  = (const float*)d_in[6];
    const float* Wkvv  = (const float*)d_in[7];
    const float* Wo    = (const float*)d_in[8];
    const float* cosT  = (const float*)d_in[9];
    const float* sinT  = (const float*)d_in[10];
    float* out = (float*)d_out;

    __half* p_hidden = (__half*)symaddr(g_hidden);
    __half* p_Wq     = (__half*)symaddr(g_Wq);
    __half* p_Wkvd   = (__half*)symaddr(g_Wkvd);
    __half* p_Wkvuv  = (__half*)symaddr(g_Wkvuv);
    __half* p_Wo     = (__half*)symaddr(g_Wo);
    __half* p_q      = (__half*)symaddr(g_q);
    __half* p_k      = (__half*)symaddr(g_k);
    __half* p_v      = (__half*)symaddr(g_v);
    float*  p_ckvraw = (float*) symaddr(g_ckv_raw);
    __half* p_ckv    = (__half*)symaddr(g_ckv);
    __half* p_attn   = (__half*)symaddr(g_attn);

    // launch 0: fused convert (Wkv_up/Wkv_v into merged buffer)
    cvt_all_kernel<<<(N4_TOT + 255) / 256, 256>>>(
        hidden, Wq, Wkvd, Wkvu, Wkvv, Wo,
        p_hidden, p_Wq, p_Wkvd, p_Wkvuv, p_Wo);

    cudaFuncSetAttribute(gemm_nt<0>, cudaFuncAttributeMaxDynamicSharedMemorySize, GEMM_SMEM);
    cudaFuncSetAttribute(gemm_nt<1>, cudaFuncAttributeMaxDynamicSharedMemorySize, GEMM_SMEM);
    cudaFuncSetAttribute(gemm_nt<3>, cudaFuncAttributeMaxDynamicSharedMemorySize, GEMM_SMEM);

    // launch 1: ckv_raw = hidden @ Wkv_down^T (f32)
    gemm_nt<0><<<dim3(Rc / 128, MSc / 128), 256, GEMM_SMEM>>>(
        p_hidden, p_Wkvd, p_ckvraw, nullptr, MSc, Rc, HIDc);
    // launch 2: rmsnorm
    rmsnorm_kernel<<<MSc, 128>>>(p_ckvraw, normw, p_ckv);
    // launch 3: merged k|v = ckv @ [Wkv_up;Wkv_v]^T -> scatter g_k/g_v (PROFILED idx 3)
    gemm_nt<3><<<dim3(NKV / 128, MSc / 128), 256, GEMM_SMEM>>>(
        p_ckv, p_Wkvuv, nullptr, nullptr, MSc, NKV, Rc);
    // launch 4: q = hidden @ Wq^T -> scatter [B,H,S,QHD]
    gemm_nt<1><<<dim3((Hh * QHDc) / 128, MSc / 128), 256, GEMM_SMEM>>>(
        p_hidden, p_Wq, nullptr, p_q, MSc, Hh * QHDc, HIDc);
    // launch 5: RoPE on q and k (fused)
    {
        int total = 2 * Bb * Hh * Ss * 32;
        rope_kernel<<<(total + 255) / 256, 256>>>(p_q, p_k, cosT, sinT);
    }
    // launch 6: attention (R7 config: 64-row tiles, 128 threads, 3 CTAs/SM)
    cudaFuncSetAttribute(attn_kernel, cudaFuncAttributeMaxDynamicSharedMemorySize,
                         ATTN_SMEM_BYTES);
    attn_kernel<<<dim3(Ss / 64, Hh, Bb), 128, ATTN_SMEM_BYTES>>>(p_q, p_k, p_v, p_attn);
    // launch 7: out = attn @ Wo^T (f32, straight to d_out)
    gemm_nt<0><<<dim3(HIDc / 128, MSc / 128), 256, GEMM_SMEM>>>(
        p_attn, p_Wo, out, nullptr, MSc, HIDc, HIDc);
}